// round 16
// baseline (speedup 1.0000x reference)
#include <cuda_runtime.h>
#include <cuda_bf16.h>
#include <cstdint>

#define NN   50000
#define NPAD 50048              // 391 * 128
#define HID  128
#define NREL 8
#define KC   32
#define NCH  4                  // 128/32
#define NMB  391
#define NSUB 8
#define NB2  (NMB * NREL * NSUB)    // 25024 buckets
#define EMAX 600000
#define ECAP 512
#define ND   (NREL * HID + HID)
#define STG  32768              // stage: [A(hi8K|lo8K) or Afp32 16K] | B_HI 8K | B_LO 8K

// ---------------- scratch ----------------
__device__ float g_t[(size_t)NPAD * HID];
__device__ float g_cnt[(size_t)NN * NREL];
__device__ __nv_bfloat16 g_xhi[(size_t)NPAD * HID];
__device__ __nv_bfloat16 g_xlo[(size_t)NPAD * HID];
__device__ __nv_bfloat16 g_bhi1[ND * HID];
__device__ __nv_bfloat16 g_blo1[ND * HID];
__device__ __nv_bfloat16 g_bhi2[ND * HID];
__device__ __nv_bfloat16 g_blo2[ND * HID];
__device__ int g_hist[NB2];
__device__ int g_cur[NB2];
__device__ int g_boff[NB2 + 1];
__device__ int4 g_edge[EMAX];

// ---------------- helpers ----------------
__device__ __forceinline__ void ldmx4(uint32_t* r, uint32_t addr) {
    asm volatile("ldmatrix.sync.aligned.m8n8.x4.shared.b16 {%0,%1,%2,%3}, [%4];"
                 : "=r"(r[0]), "=r"(r[1]), "=r"(r[2]), "=r"(r[3]) : "r"(addr));
}
__device__ __forceinline__ void mma16816(float* c, const uint32_t* a, const uint32_t* b) {
    asm volatile("mma.sync.aligned.m16n8k16.row.col.f32.bf16.bf16.f32 "
                 "{%0,%1,%2,%3}, {%4,%5,%6,%7}, {%8,%9}, {%0,%1,%2,%3};"
                 : "+f"(c[0]), "+f"(c[1]), "+f"(c[2]), "+f"(c[3])
                 : "r"(a[0]), "r"(a[1]), "r"(a[2]), "r"(a[3]), "r"(b[0]), "r"(b[1]));
}
__device__ __forceinline__ uint32_t smem_u32(const void* p) {
    uint32_t a;
    asm("{ .reg .u64 t; cvta.to.shared.u64 t, %1; cvt.u32.u64 %0, t; }" : "=r"(a) : "l"(p));
    return a;
}
__device__ __forceinline__ void cp_async16(uint32_t saddr, const void* gaddr) {
    asm volatile("cp.async.cg.shared.global [%0], [%1], 16;" :: "r"(saddr), "l"(gaddr));
}
template <int N> __device__ __forceinline__ void cpwait() {
    asm volatile("cp.async.wait_group %0;" :: "n"(N) : "memory");
}
__device__ __forceinline__ void cpcommit() {
    asm volatile("cp.async.commit_group;" ::: "memory");
}
__device__ __forceinline__ void red_add_f32(float* p, float v) {
    asm volatile("red.global.add.f32 [%0], %1;" :: "l"(p), "f"(v) : "memory");
}
__device__ __forceinline__ void red_add_s32(int* p, int v) {
    asm volatile("red.global.add.s32 [%0], %1;" :: "l"(p), "r"(v) : "memory");
}
__device__ __forceinline__ void split4(float4 v, int do_relu, uint2& hv, uint2& lv) {
    if (do_relu) {
        v.x = fmaxf(v.x, 0.f); v.y = fmaxf(v.y, 0.f);
        v.z = fmaxf(v.z, 0.f); v.w = fmaxf(v.w, 0.f);
    }
    __nv_bfloat162 h01 = __floats2bfloat162_rn(v.x, v.y);
    __nv_bfloat162 h23 = __floats2bfloat162_rn(v.z, v.w);
    __nv_bfloat162 l01 = __floats2bfloat162_rn(v.x - __bfloat162float(h01.x),
                                               v.y - __bfloat162float(h01.y));
    __nv_bfloat162 l23 = __floats2bfloat162_rn(v.z - __bfloat162float(h23.x),
                                               v.w - __bfloat162float(h23.y));
    hv.x = *(const uint32_t*)&h01; hv.y = *(const uint32_t*)&h23;
    lv.x = *(const uint32_t*)&l01; lv.y = *(const uint32_t*)&l23;
}
__device__ __forceinline__ void xsplit_piece(int i, const float* __restrict__ src, int srows,
                                             int do_relu, __nv_bfloat16* __restrict__ hi,
                                             __nv_bfloat16* __restrict__ lo) {
    int row = i >> 5;
    float4 v = make_float4(0.f, 0.f, 0.f, 0.f);
    if (row < srows) v = ((const float4*)src)[i];
    uint2 hv, lv;
    split4(v, do_relu, hv, lv);
    ((uint2*)hi)[i] = hv;
    ((uint2*)lo)[i] = lv;
}

// ---------------- small kernels ----------------
__global__ void counthist_kernel(const int* __restrict__ src, const int* __restrict__ dst,
                                 const int* __restrict__ rel, int E,
                                 float* __restrict__ cnt, int* __restrict__ hist) {
    int base = (blockIdx.x * blockDim.x + threadIdx.x) * 4;
#pragma unroll
    for (int i = 0; i < 4; i++) {
        int e = base + i;
        if (e < E) {
            int s = __ldg(src + e);
            int r = __ldg(rel + e);
            red_add_f32(&cnt[__ldg(dst + e) * NREL + r], 1.0f);
            red_add_s32(&hist[((s >> 7) * NREL + r) * NSUB + ((s >> 4) & 7)], 1);
        }
    }
}
#define VPT 25
__global__ void scan_kernel(const int* __restrict__ hist, int* __restrict__ boff,
                            int* __restrict__ cur) {
    __shared__ int part[1024];
    int t = threadIdx.x;
    // zero cur (reorder's counters) — saves a memset launch
    for (int b = t; b < NB2; b += 1024) cur[b] = 0;
    int vals[VPT];
    int s = 0;
#pragma unroll
    for (int i = 0; i < VPT; i++) {
        int b = t * VPT + i;
        vals[i] = (b < NB2) ? hist[b] : 0;
        s += vals[i];
    }
    part[t] = s;
    __syncthreads();
    for (int off = 1; off < 1024; off <<= 1) {
        int v = (t >= off) ? part[t - off] : 0;
        __syncthreads();
        part[t] += v;
        __syncthreads();
    }
    int run = (t > 0) ? part[t - 1] : 0;
#pragma unroll
    for (int i = 0; i < VPT; i++) {
        int b = t * VPT + i;
        if (b <= NB2) boff[b] = run;
        run += vals[i];
    }
    if (t == 1023) boff[NB2] = run;
}

// merged: reorder || bconv x2 || binit x2 || xsplit(layer1)
#define RBLK ((EMAX + 511) / 512)
#define BCONV_BLKS ((ND * HID + 255) / 256)
#define BINIT_T_BLKS ((NPAD * 32 + 255) / 256)
#define BINIT_O_BLKS ((NN * 32 + 255) / 256)
#define XS_BLKS ((NPAD * 32 + 255) / 256)
__global__ void prep_kernel(const int* __restrict__ src, const int* __restrict__ dst,
                            const int* __restrict__ rel, int E,
                            const int* __restrict__ boff, int* __restrict__ cur,
                            const float* __restrict__ cnt, int4* __restrict__ edge,
                            const float* __restrict__ W1, const float* __restrict__ root1,
                            const float* __restrict__ W2, const float* __restrict__ root2,
                            const float* __restrict__ b1, const float* __restrict__ b2,
                            __nv_bfloat16* __restrict__ bhi1, __nv_bfloat16* __restrict__ blo1,
                            __nv_bfloat16* __restrict__ bhi2, __nv_bfloat16* __restrict__ blo2,
                            float* __restrict__ t, float* __restrict__ out,
                            const float* __restrict__ x0,
                            __nv_bfloat16* __restrict__ xhi, __nv_bfloat16* __restrict__ xlo) {
    int bx = blockIdx.x;
    if (bx < RBLK) {
        int base = (bx * 256 + threadIdx.x) * 2;
        int s[2], d[2], r[2], pos[2];
        float sc[2];
        int n = min(2, E - base);
        if (n <= 0) return;
#pragma unroll
        for (int i = 0; i < 2; i++) {
            if (i < n) {
                s[i] = __ldg(src + base + i);
                d[i] = __ldg(dst + base + i);
                r[i] = __ldg(rel + base + i);
            }
        }
#pragma unroll
        for (int i = 0; i < 2; i++) {
            if (i < n) {
                int b = ((s[i] >> 7) * NREL + r[i]) * NSUB + ((s[i] >> 4) & 7);
                pos[i] = __ldg(boff + b) + atomicAdd(&cur[b], 1);
                sc[i] = 1.0f / fmaxf(__ldg(cnt + d[i] * NREL + r[i]), 1.0f);
            }
        }
#pragma unroll
        for (int i = 0; i < 2; i++)
            if (i < n) edge[pos[i]] = make_int4(s[i], d[i], __float_as_int(sc[i]), 0);
        return;
    }
    bx -= RBLK;
    if (bx < 2 * BCONV_BLKS) {
        int layer = bx >= BCONV_BLKS;
        const float* W = layer ? W2 : W1;
        const float* root = layer ? root2 : root1;
        __nv_bfloat16* bhi = layer ? bhi2 : bhi1;
        __nv_bfloat16* blo = layer ? blo2 : blo1;
        int i = (bx - layer * BCONV_BLKS) * 256 + threadIdx.x;
        if (i >= ND * HID) return;
        int nn = i >> 7, k = i & 127;
        float v = (nn < NREL * HID) ? W[((size_t)(nn >> 7) * HID + k) * HID + (nn & 127)]
                                    : root[(size_t)k * HID + (nn - NREL * HID)];
        __nv_bfloat16 h = __float2bfloat16(v);
        bhi[i] = h;
        blo[i] = __float2bfloat16(v - __bfloat162float(h));
        return;
    }
    bx -= 2 * BCONV_BLKS;
    if (bx < BINIT_T_BLKS) {
        int i = bx * 256 + threadIdx.x;
        if (i < NPAD * 32) ((float4*)t)[i] = ((const float4*)b1)[i & 31];
        return;
    }
    bx -= BINIT_T_BLKS;
    if (bx < BINIT_O_BLKS) {
        int i = bx * 256 + threadIdx.x;
        if (i < NN * 32) ((float4*)out)[i] = ((const float4*)b2)[i & 31];
        return;
    }
    bx -= BINIT_O_BLKS;
    int i = bx * 256 + threadIdx.x;
    if (i < NPAD * 32) xsplit_piece(i, x0, NN, 0, xhi, xlo);
}

// ---------------- fused bf16x3 GEMM + scatter ----------------
// CVT=0: pre-split A, 3-stage pipeline. smem: 3x32KB stages + 8KB edges = 104KB.
// CVT=1: fp32 A converted in-kernel. smem: 2x32KB stages + 16KB CONV + 8KB edges = 88KB.
// Packed-pair swizzle: addr(r, kb) = (r>>1)*128 + (((r&1)*64 + kb) ^ (((r>>1)&7)*16))
template <int CVT>
__global__ void __launch_bounds__(256, 2)
gemm_fused(const float* __restrict__ Xf,
           const __nv_bfloat16* __restrict__ Ahi, const __nv_bfloat16* __restrict__ Alo,
           int xrows, int do_relu,
           const __nv_bfloat16* __restrict__ Bhi, const __nv_bfloat16* __restrict__ Blo,
           float* __restrict__ acc_out, int acc_rows,
           const int4* __restrict__ edge, const int* __restrict__ boff) {
    extern __shared__ char smem[];
    const uint32_t sbase = smem_u32(smem);
    constexpr uint32_t CONV = 2 * STG;                       // CVT only
    constexpr uint32_t EDG = CVT ? (2 * STG + 16384) : (3 * STG);
    float* stile = (float*)smem;
    const int4* sedge = (const int4*)(smem + EDG);

    const int tid = threadIdx.x, wid = tid >> 5, lid = tid & 31;
    const int nt = blockIdx.x;                 // 0..7 relations, 8 root
    const int block_row = blockIdx.y * 128;
    const int bcol = nt * 128;
    const int wm = wid >> 2, wn = wid & 3;

    auto issue_chunk = [&](uint32_t stg, int c) {
#pragma unroll
        for (int i = 0; i < 8; i++) {
            int idx = tid + i * 256;            // 0..2047
            if (CVT) {
                if (idx < 1024) {               // A fp32: linear rows of 128B
                    int r = idx >> 3, j = idx & 7;
                    int grow = block_row + r;
                    uint32_t dst = stg + (uint32_t)(r * 128 + j * 16);
                    if (grow < xrows)
                        cp_async16(dst, Xf + (size_t)grow * HID + c * KC + j * 4);
                    else
                        *(uint4*)(smem + (dst - sbase)) = make_uint4(0, 0, 0, 0);
                } else {                        // B hi/lo bf16, swizzled
                    int q = idx - 1024;
                    int comp = q >> 9;
                    int r = (q >> 2) & 127;
                    int j = q & 3;
                    const __nv_bfloat16* srcp = (comp ? Blo : Bhi)
                        + (size_t)(bcol + r) * HID + c * KC + j * 8;
                    uint32_t a = (uint32_t)(r >> 1) * 128
                        + ((((uint32_t)(r & 1)) * 64 + (uint32_t)j * 16)
                           ^ (((uint32_t)(r >> 1) & 7) * 16));
                    cp_async16(stg + 16384u + (comp ? 8192u : 0u) + a, srcp);
                }
            } else {
                int half = idx >> 10;               // 0 = A, 1 = B
                int q = idx & 1023;
                int comp = q >> 9;                  // 0 hi, 1 lo
                int r = (q >> 2) & 127;
                int j = q & 3;
                const __nv_bfloat16* srcp;
                if (half == 0)
                    srcp = (comp ? Alo : Ahi) + (size_t)(block_row + r) * HID + c * KC + j * 8;
                else
                    srcp = (comp ? Blo : Bhi) + (size_t)(bcol + r) * HID + c * KC + j * 8;
                uint32_t a = (uint32_t)(r >> 1) * 128
                    + ((((uint32_t)(r & 1)) * 64 + (uint32_t)j * 16)
                       ^ (((uint32_t)(r >> 1) & 7) * 16));
                uint32_t base = (half ? 16384u : 0u) + (comp ? 8192u : 0u);
                cp_async16(stg + base + a, srcp);
            }
        }
    };

    // convert fp32 stage A -> bf16 hi/lo into CONV (out-of-place, CVT only)
    auto convert_chunk = [&](uint32_t stg) {
#pragma unroll
        for (int i = 0; i < 4; i++) {
            int idx = tid + i * 256;            // 0..1023
            int r = idx >> 3, j = idx & 7;
            float4 v = *(const float4*)(smem + (stg - sbase) + idx * 16);
            uint2 hv, lv;
            split4(v, do_relu, hv, lv);
            uint32_t a = (uint32_t)(r >> 1) * 128
                + ((((uint32_t)(r & 1)) * 64 + (uint32_t)j * 8)
                   ^ (((uint32_t)(r >> 1) & 7) * 16));
            *(uint2*)(smem + CONV + a) = hv;
            *(uint2*)(smem + CONV + 8192 + a) = lv;
        }
    };

    // ---- prologue: edges + first chunks ----
    int e0 = 0, ecnt = 0;
    if (nt < 8) {
        const int b8 = (blockIdx.y * NREL + nt) * NSUB;
        e0 = boff[b8];
        ecnt = boff[b8 + NSUB] - e0;
        int pn = min(ecnt, ECAP);
        for (int i = tid; i < pn; i += 256)
            cp_async16(sbase + EDG + i * 16, edge + e0 + i);
    }
    issue_chunk(sbase + 0 * STG, 0); cpcommit();
    issue_chunk(sbase + 1 * STG, 1); cpcommit();
    if (!CVT) { issue_chunk(sbase + 2 * STG, 2); cpcommit(); }

    // per-lane fragment geometry
    const int arow = lid & 15;
    const uint32_t akoff = (uint32_t)(lid >> 4) * 16;
    const uint32_t asel = (uint32_t)(arow & 1) * 64;
    const uint32_t axorn = (uint32_t)((arow >> 1) & 7) * 16;
    const uint32_t abase = (uint32_t)(wm * 32 + (arow >> 1)) * 128;
    const int brow = (lid & 7) + ((lid >> 4) * 8);
    const uint32_t bkoff = (uint32_t)((lid >> 3) & 1) * 16;
    const uint32_t bsel = (uint32_t)(brow & 1) * 64;
    const uint32_t bxorn = (uint32_t)((brow >> 1) & 7) * 16;
    const uint32_t bbase = (uint32_t)(wn * 16 + (brow >> 1)) * 128;

    float acc[4][4][4];
#pragma unroll
    for (int i = 0; i < 4; i++)
#pragma unroll
        for (int j = 0; j < 4; j++)
#pragma unroll
            for (int v = 0; v < 4; v++) acc[i][j][v] = 0.0f;

    // areg = region holding A_HI (A_LO at +8192); breg = region holding B_HI (B_LO at +8192)
    auto compute_chunk = [&](uint32_t areg, uint32_t breg) {
#pragma unroll
        for (int kk = 0; kk < 2; kk++) {
            uint32_t af[4][4], bf[4][2];
            uint32_t ka = (uint32_t)kk * 32 + akoff;
            uint32_t kb = (uint32_t)kk * 32 + bkoff;

#pragma unroll
            for (int mt = 0; mt < 4; mt++)
                ldmx4(af[mt], areg + abase + (uint32_t)mt * 1024 + ((asel + ka) ^ axorn));
#pragma unroll
            for (int p = 0; p < 2; p++) {
                uint32_t r4[4];
                ldmx4(r4, breg + 8192u + bbase + (uint32_t)p * 1024 + ((bsel + kb) ^ bxorn));
                bf[2 * p][0] = r4[0]; bf[2 * p][1] = r4[1];
                bf[2 * p + 1][0] = r4[2]; bf[2 * p + 1][1] = r4[3];
            }
#pragma unroll
            for (int mt = 0; mt < 4; mt++)
#pragma unroll
                for (int j = 0; j < 4; j++) mma16816(acc[mt][j], af[mt], bf[j]);

#pragma unroll
            for (int p = 0; p < 2; p++) {
                uint32_t r4[4];
                ldmx4(r4, breg + bbase + (uint32_t)p * 1024 + ((bsel + kb) ^ bxorn));
                bf[2 * p][0] = r4[0]; bf[2 * p][1] = r4[1];
                bf[2 * p + 1][0] = r4[2]; bf[2 * p + 1][1] = r4[3];
            }
#pragma unroll
            for (int mt = 0; mt < 4; mt++)
#pragma unroll
                for (int j = 0; j < 4; j++) mma16816(acc[mt][j], af[mt], bf[j]);

#pragma unroll
            for (int mt = 0; mt < 4; mt++)
                ldmx4(af[mt], areg + 8192u + abase + (uint32_t)mt * 1024 + ((asel + ka) ^ axorn));
#pragma unroll
            for (int mt = 0; mt < 4; mt++)
#pragma unroll
                for (int j = 0; j < 4; j++) mma16816(acc[mt][j], af[mt], bf[j]);
        }
    };

    if (CVT) {
        // 2 stages + CONV
        cpwait<1>(); __syncthreads();
        convert_chunk(sbase + 0 * STG); __syncthreads();
        compute_chunk(sbase + CONV, sbase + 0 * STG + 16384u);
        __syncthreads();
        issue_chunk(sbase + 0 * STG, 2); cpcommit();
        cpwait<1>(); __syncthreads();
        convert_chunk(sbase + 1 * STG); __syncthreads();
        compute_chunk(sbase + CONV, sbase + 1 * STG + 16384u);
        __syncthreads();
        issue_chunk(sbase + 1 * STG, 3); cpcommit();
        cpwait<1>(); __syncthreads();
        convert_chunk(sbase + 0 * STG); __syncthreads();
        compute_chunk(sbase + CONV, sbase + 0 * STG + 16384u);
        cpwait<0>(); __syncthreads();
        convert_chunk(sbase + 1 * STG); __syncthreads();
        compute_chunk(sbase + CONV, sbase + 1 * STG + 16384u);
    } else {
        // 3 stages, pre-split A
        cpwait<2>(); __syncthreads();
        compute_chunk(sbase + 0 * STG, sbase + 0 * STG + 16384u);
        __syncthreads();
        issue_chunk(sbase + 0 * STG, 3); cpcommit();
        cpwait<2>(); __syncthreads();
        compute_chunk(sbase + 1 * STG, sbase + 1 * STG + 16384u);
        cpwait<1>(); __syncthreads();
        compute_chunk(sbase + 2 * STG, sbase + 2 * STG + 16384u);
        cpwait<0>(); __syncthreads();
        compute_chunk(sbase + 0 * STG, sbase + 0 * STG + 16384u);
    }

    if (nt == 8) {
#pragma unroll
        for (int mt = 0; mt < 4; mt++) {
            int r0 = block_row + wm * 64 + mt * 16 + (lid >> 2);
#pragma unroll
            for (int j = 0; j < 4; j++) {
                int col = wn * 32 + j * 8 + (lid & 3) * 2;
                if (r0 < acc_rows) {
                    float* p = acc_out + (size_t)r0 * HID + col;
                    asm volatile("red.global.add.v2.f32 [%0], {%1, %2};"
                                 :: "l"(p), "f"(acc[mt][j][0]), "f"(acc[mt][j][1]) : "memory");
                }
                if (r0 + 8 < acc_rows) {
                    float* p = acc_out + (size_t)(r0 + 8) * HID + col;
                    asm volatile("red.global.add.v2.f32 [%0], {%1, %2};"
                                 :: "l"(p), "f"(acc[mt][j][2]), "f"(acc[mt][j][3]) : "memory");
                }
            }
        }
        return;
    }

    // relation tile: stage fp32 tile to smem (reuses stages), scatter bucket edges
    __syncthreads();
#pragma unroll
    for (int mt = 0; mt < 4; mt++) {
        int r0 = wm * 64 + mt * 16 + (lid >> 2);
#pragma unroll
        for (int j = 0; j < 4; j++) {
            int col = wn * 32 + j * 8 + (lid & 3) * 2;
            *(float2*)(stile + r0 * 128 + col)       = make_float2(acc[mt][j][0], acc[mt][j][1]);
            *(float2*)(stile + (r0 + 8) * 128 + col) = make_float2(acc[mt][j][2], acc[mt][j][3]);
        }
    }
    __syncthreads();

    const int pn = min(ecnt, ECAP);
    for (int e = wid; e < pn; e += 8) {
        int4 ed = sedge[e];
        float sc = __int_as_float(ed.z);
        const float4 v = *(const float4*)(stile + (ed.x - block_row) * 128 + lid * 4);
        float4* p = (float4*)(acc_out + (size_t)ed.y * HID) + lid;
        asm volatile("red.global.add.v4.f32 [%0], {%1, %2, %3, %4};"
                     :: "l"(p), "f"(v.x * sc), "f"(v.y * sc), "f"(v.z * sc), "f"(v.w * sc)
                     : "memory");
    }
    for (int e = ECAP + wid; e < ecnt; e += 8) {
        int4 ed = edge[e0 + e];
        float sc = __int_as_float(ed.z);
        const float4 v = *(const float4*)(stile + (ed.x - block_row) * 128 + lid * 4);
        float4* p = (float4*)(acc_out + (size_t)ed.y * HID) + lid;
        asm volatile("red.global.add.v4.f32 [%0], {%1, %2, %3, %4};"
                     :: "l"(p), "f"(v.x * sc), "f"(v.y * sc), "f"(v.z * sc), "f"(v.w * sc)
                     : "memory");
    }
}

// ---------------- launch ----------------
extern "C" void kernel_launch(void* const* d_in, const int* in_sizes, int n_in,
                              void* d_out, int out_size) {
    const int* edge_index = (const int*)d_in[0];
    const int* edge_type  = (const int*)d_in[1];
    const float* node_emb = (const float*)d_in[2];
    const float* W1    = (const float*)d_in[3];
    const float* root1 = (const float*)d_in[4];
    const float* b1    = (const float*)d_in[5];
    const float* W2    = (const float*)d_in[6];
    const float* root2 = (const float*)d_in[7];
    const float* b2    = (const float*)d_in[8];
    float* out = (float*)d_out;

    const int E = in_sizes[0] / 2;
    const int* src = edge_index;
    const int* dst = edge_index + E;

    float *t, *cnt;
    __nv_bfloat16 *xhi, *xlo, *bhi1, *blo1, *bhi2, *blo2;
    int *hist, *cur, *boff;
    int4* edge;
    cudaGetSymbolAddress((void**)&t,    g_t);
    cudaGetSymbolAddress((void**)&cnt,  g_cnt);
    cudaGetSymbolAddress((void**)&xhi,  g_xhi);
    cudaGetSymbolAddress((void**)&xlo,  g_xlo);
    cudaGetSymbolAddress((void**)&bhi1, g_bhi1);
    cudaGetSymbolAddress((void**)&blo1, g_blo1);
    cudaGetSymbolAddress((void**)&bhi2, g_bhi2);
    cudaGetSymbolAddress((void**)&blo2, g_blo2);
    cudaGetSymbolAddress((void**)&hist, g_hist);
    cudaGetSymbolAddress((void**)&cur,  g_cur);
    cudaGetSymbolAddress((void**)&boff, g_boff);
    cudaGetSymbolAddress((void**)&edge, g_edge);

    const int T = 256;
    const dim3 gemm_grid(9, NMB);
    const int SMEM0 = 3 * STG + ECAP * 16;              // 106496
    const int SMEM1 = 2 * STG + 16384 + ECAP * 16;      // 90112
    cudaFuncSetAttribute(gemm_fused<0>, cudaFuncAttributeMaxDynamicSharedMemorySize, SMEM0);
    cudaFuncSetAttribute(gemm_fused<1>, cudaFuncAttributeMaxDynamicSharedMemorySize, SMEM1);

    // ---- prep ----
    cudaMemsetAsync(cnt, 0, sizeof(float) * (size_t)NN * NREL, 0);
    cudaMemsetAsync(hist, 0, sizeof(int) * NB2, 0);
    counthist_kernel<<<(E + T * 4 - 1) / (T * 4), T>>>(src, dst, edge_type, E, cnt, hist);
    scan_kernel<<<1, 1024>>>(hist, boff, cur);
    prep_kernel<<<RBLK + 2 * BCONV_BLKS + BINIT_T_BLKS + BINIT_O_BLKS + XS_BLKS, T>>>(
        src, dst, edge_type, E, boff, cur, cnt, edge,
        W1, root1, W2, root2, b1, b2, bhi1, blo1, bhi2, blo2, t, out,
        node_emb, xhi, xlo);

    // ---- layer 1: pre-split A, 3-stage pipeline ----
    gemm_fused<0><<<gemm_grid, T, SMEM0>>>(nullptr, xhi, xlo, NPAD, 0,
                                           bhi1, blo1, t, NPAD, edge, boff);
    // ---- layer 2: fp32 t converted in-kernel (relu fused), no xsplit2 ----
    gemm_fused<1><<<gemm_grid, T, SMEM1>>>(t, nullptr, nullptr, NPAD, 1,
                                           bhi2, blo2, out, NN, edge, boff);
}

// round 17
// speedup vs baseline: 1.0676x; 1.0676x over previous
#include <cuda_runtime.h>
#include <cuda_bf16.h>
#include <cstdint>

#define NN   50000
#define NPAD 50048              // 391 * 128
#define HID  128
#define NREL 8
#define KC   32
#define NCH  4                  // 128/32
#define NMB  391
#define NSUB 8
#define NB2  (NMB * NREL * NSUB)    // 25024 buckets
#define EMAX 600000
#define ECAP 512
#define ND   (NREL * HID + HID)
#define STG  32768              // stage: A_HI 8K | A_LO 8K | B_HI 8K | B_LO 8K

// ---------------- scratch ----------------
__device__ float g_t[(size_t)NPAD * HID];
__device__ float g_cnt[(size_t)NN * NREL];
__device__ __nv_bfloat16 g_xhi[(size_t)NPAD * HID];
__device__ __nv_bfloat16 g_xlo[(size_t)NPAD * HID];
__device__ __nv_bfloat16 g_bhi1[ND * HID];
__device__ __nv_bfloat16 g_blo1[ND * HID];
__device__ __nv_bfloat16 g_bhi2[ND * HID];
__device__ __nv_bfloat16 g_blo2[ND * HID];
__device__ int g_hist[NB2];
__device__ int g_cur[NB2];
__device__ int g_boff[NB2 + 1];
__device__ int4 g_edge[EMAX];

// ---------------- helpers ----------------
__device__ __forceinline__ void ldmx4(uint32_t* r, uint32_t addr) {
    asm volatile("ldmatrix.sync.aligned.m8n8.x4.shared.b16 {%0,%1,%2,%3}, [%4];"
                 : "=r"(r[0]), "=r"(r[1]), "=r"(r[2]), "=r"(r[3]) : "r"(addr));
}
__device__ __forceinline__ void mma16816(float* c, const uint32_t* a, const uint32_t* b) {
    asm volatile("mma.sync.aligned.m16n8k16.row.col.f32.bf16.bf16.f32 "
                 "{%0,%1,%2,%3}, {%4,%5,%6,%7}, {%8,%9}, {%0,%1,%2,%3};"
                 : "+f"(c[0]), "+f"(c[1]), "+f"(c[2]), "+f"(c[3])
                 : "r"(a[0]), "r"(a[1]), "r"(a[2]), "r"(a[3]), "r"(b[0]), "r"(b[1]));
}
__device__ __forceinline__ uint32_t smem_u32(const void* p) {
    uint32_t a;
    asm("{ .reg .u64 t; cvta.to.shared.u64 t, %1; cvt.u32.u64 %0, t; }" : "=r"(a) : "l"(p));
    return a;
}
__device__ __forceinline__ void cp_async16(uint32_t saddr, const void* gaddr) {
    asm volatile("cp.async.cg.shared.global [%0], [%1], 16;" :: "r"(saddr), "l"(gaddr));
}
template <int N> __device__ __forceinline__ void cpwait() {
    asm volatile("cp.async.wait_group %0;" :: "n"(N) : "memory");
}
__device__ __forceinline__ void cpcommit() {
    asm volatile("cp.async.commit_group;" ::: "memory");
}
__device__ __forceinline__ void red_add_f32(float* p, float v) {
    asm volatile("red.global.add.f32 [%0], %1;" :: "l"(p), "f"(v) : "memory");
}
__device__ __forceinline__ void red_add_s32(int* p, int v) {
    asm volatile("red.global.add.s32 [%0], %1;" :: "l"(p), "r"(v) : "memory");
}
// fp32 float4 -> bf16x2 hi/lo split (+optional relu), write to [row][128] arrays
__device__ __forceinline__ void xsplit_piece(int i, const float* __restrict__ src, int srows,
                                             int do_relu, __nv_bfloat16* __restrict__ hi,
                                             __nv_bfloat16* __restrict__ lo) {
    int row = i >> 5;
    float4 v = make_float4(0.f, 0.f, 0.f, 0.f);
    if (row < srows) v = ((const float4*)src)[i];
    if (do_relu) {
        v.x = fmaxf(v.x, 0.f); v.y = fmaxf(v.y, 0.f);
        v.z = fmaxf(v.z, 0.f); v.w = fmaxf(v.w, 0.f);
    }
    __nv_bfloat162 h01 = __floats2bfloat162_rn(v.x, v.y);
    __nv_bfloat162 h23 = __floats2bfloat162_rn(v.z, v.w);
    __nv_bfloat162 l01 = __floats2bfloat162_rn(v.x - __bfloat162float(h01.x),
                                               v.y - __bfloat162float(h01.y));
    __nv_bfloat162 l23 = __floats2bfloat162_rn(v.z - __bfloat162float(h23.x),
                                               v.w - __bfloat162float(h23.y));
    uint2 hv, lv;
    hv.x = *(const uint32_t*)&h01; hv.y = *(const uint32_t*)&h23;
    lv.x = *(const uint32_t*)&l01; lv.y = *(const uint32_t*)&l23;
    ((uint2*)hi)[i] = hv;
    ((uint2*)lo)[i] = lv;
}

// ---------------- small kernels ----------------
__global__ void counthist_kernel(const int* __restrict__ src, const int* __restrict__ dst,
                                 const int* __restrict__ rel, int E,
                                 float* __restrict__ cnt, int* __restrict__ hist) {
    int base = (blockIdx.x * blockDim.x + threadIdx.x) * 4;
#pragma unroll
    for (int i = 0; i < 4; i++) {
        int e = base + i;
        if (e < E) {
            int s = __ldg(src + e);
            int r = __ldg(rel + e);
            red_add_f32(&cnt[__ldg(dst + e) * NREL + r], 1.0f);
            red_add_s32(&hist[((s >> 7) * NREL + r) * NSUB + ((s >> 4) & 7)], 1);
        }
    }
}
#define VPT 25
__global__ void scan_kernel(const int* __restrict__ hist, int* __restrict__ boff,
                            int* __restrict__ cur) {
    __shared__ int part[1024];
    int t = threadIdx.x;
    for (int b = t; b < NB2; b += 1024) cur[b] = 0;   // fold cur-zeroing here
    int vals[VPT];
    int s = 0;
#pragma unroll
    for (int i = 0; i < VPT; i++) {
        int b = t * VPT + i;
        vals[i] = (b < NB2) ? hist[b] : 0;
        s += vals[i];
    }
    part[t] = s;
    __syncthreads();
    for (int off = 1; off < 1024; off <<= 1) {
        int v = (t >= off) ? part[t - off] : 0;
        __syncthreads();
        part[t] += v;
        __syncthreads();
    }
    int run = (t > 0) ? part[t - 1] : 0;
#pragma unroll
    for (int i = 0; i < VPT; i++) {
        int b = t * VPT + i;
        if (b <= NB2) boff[b] = run;
        run += vals[i];
    }
    if (t == 1023) boff[NB2] = run;
}

// merged: reorder || bconv x2 || binit x2 || xsplit(layer1)
#define RBLK ((EMAX + 511) / 512)
#define BCONV_BLKS ((ND * HID + 255) / 256)
#define BINIT_T_BLKS ((NPAD * 32 + 255) / 256)
#define BINIT_O_BLKS ((NN * 32 + 255) / 256)
#define XS_BLKS ((NPAD * 32 + 255) / 256)
__global__ void prep_kernel(const int* __restrict__ src, const int* __restrict__ dst,
                            const int* __restrict__ rel, int E,
                            const int* __restrict__ boff, int* __restrict__ cur,
                            const float* __restrict__ cnt, int4* __restrict__ edge,
                            const float* __restrict__ W1, const float* __restrict__ root1,
                            const float* __restrict__ W2, const float* __restrict__ root2,
                            const float* __restrict__ b1, const float* __restrict__ b2,
                            __nv_bfloat16* __restrict__ bhi1, __nv_bfloat16* __restrict__ blo1,
                            __nv_bfloat16* __restrict__ bhi2, __nv_bfloat16* __restrict__ blo2,
                            float* __restrict__ t, float* __restrict__ out,
                            const float* __restrict__ x0,
                            __nv_bfloat16* __restrict__ xhi, __nv_bfloat16* __restrict__ xlo) {
    int bx = blockIdx.x;
    if (bx < RBLK) {
        int base = (bx * 256 + threadIdx.x) * 2;
        int s[2], d[2], r[2], pos[2];
        float sc[2];
        int n = min(2, E - base);
        if (n <= 0) return;
#pragma unroll
        for (int i = 0; i < 2; i++) {
            if (i < n) {
                s[i] = __ldg(src + base + i);
                d[i] = __ldg(dst + base + i);
                r[i] = __ldg(rel + base + i);
            }
        }
#pragma unroll
        for (int i = 0; i < 2; i++) {
            if (i < n) {
                int b = ((s[i] >> 7) * NREL + r[i]) * NSUB + ((s[i] >> 4) & 7);
                pos[i] = __ldg(boff + b) + atomicAdd(&cur[b], 1);
                sc[i] = 1.0f / fmaxf(__ldg(cnt + d[i] * NREL + r[i]), 1.0f);
            }
        }
#pragma unroll
        for (int i = 0; i < 2; i++)
            if (i < n) edge[pos[i]] = make_int4(s[i], d[i], __float_as_int(sc[i]), 0);
        return;
    }
    bx -= RBLK;
    if (bx < 2 * BCONV_BLKS) {
        int layer = bx >= BCONV_BLKS;
        const float* W = layer ? W2 : W1;
        const float* root = layer ? root2 : root1;
        __nv_bfloat16* bhi = layer ? bhi2 : bhi1;
        __nv_bfloat16* blo = layer ? blo2 : blo1;
        int i = (bx - layer * BCONV_BLKS) * 256 + threadIdx.x;
        if (i >= ND * HID) return;
        int nn = i >> 7, k = i & 127;
        float v = (nn < NREL * HID) ? W[((size_t)(nn >> 7) * HID + k) * HID + (nn & 127)]
                                    : root[(size_t)k * HID + (nn - NREL * HID)];
        __nv_bfloat16 h = __float2bfloat16(v);
        bhi[i] = h;
        blo[i] = __float2bfloat16(v - __bfloat162float(h));
        return;
    }
    bx -= 2 * BCONV_BLKS;
    if (bx < BINIT_T_BLKS) {
        int i = bx * 256 + threadIdx.x;
        if (i < NPAD * 32) ((float4*)t)[i] = ((const float4*)b1)[i & 31];
        return;
    }
    bx -= BINIT_T_BLKS;
    if (bx < BINIT_O_BLKS) {
        int i = bx * 256 + threadIdx.x;
        if (i < NN * 32) ((float4*)out)[i] = ((const float4*)b2)[i & 31];
        return;
    }
    bx -= BINIT_O_BLKS;
    int i = bx * 256 + threadIdx.x;
    if (i < NPAD * 32) xsplit_piece(i, x0, NN, 0, xhi, xlo);
}

// layer-2 A split: relu(t) -> xhi/xlo
__global__ void xsplit2_kernel(const float* __restrict__ t,
                               __nv_bfloat16* __restrict__ xhi, __nv_bfloat16* __restrict__ xlo) {
    int i = blockIdx.x * blockDim.x + threadIdx.x;
    if (i < NPAD * 32) xsplit_piece(i, t, NN, 1, xhi, xlo);
}

// ---------------- fused bf16x3 GEMM (3-stage cp.async pipeline) + scatter ----------------
// smem: 3 stages x 32KB @0, edges 8KB @98304. stile (64KB) reuses stages 0-1.
// Packed-pair swizzle for 128r x 32k bf16 tiles (64B rows, 2 rows per 128B line):
//   addr(row, kb) = (row>>1)*128 + (((row&1)*64 + kb) ^ (((row>>1)&7)*16))
__global__ void __launch_bounds__(256, 2)
gemm_fused(const __nv_bfloat16* __restrict__ Ahi, const __nv_bfloat16* __restrict__ Alo,
           const __nv_bfloat16* __restrict__ Bhi, const __nv_bfloat16* __restrict__ Blo,
           float* __restrict__ acc_out, int acc_rows,
           const int4* __restrict__ edge, const int* __restrict__ boff) {
    extern __shared__ char smem[];
    const uint32_t sbase = smem_u32(smem);
    const uint32_t EDG = 3 * STG;
    float* stile = (float*)smem;
    const int4* sedge = (const int4*)(smem + EDG);

    const int tid = threadIdx.x, wid = tid >> 5, lid = tid & 31;
    const int nt = blockIdx.x;                 // 0..7 relations, 8 root
    const int block_row = blockIdx.y * 128;
    const int bcol = nt * 128;
    const int wm = wid >> 2, wn = wid & 3;

    auto issue_chunk = [&](uint32_t stg, int c) {
#pragma unroll
        for (int i = 0; i < 8; i++) {
            int idx = tid + i * 256;            // 0..2047
            int half = idx >> 10;               // 0 = A, 1 = B
            int q = idx & 1023;
            int comp = q >> 9;                  // 0 hi, 1 lo
            int r = (q >> 2) & 127;
            int j = q & 3;                      // 16B piece within 64B row
            const __nv_bfloat16* srcp;
            if (half == 0) srcp = (comp ? Alo : Ahi) + (size_t)(block_row + r) * HID + c * KC + j * 8;
            else           srcp = (comp ? Blo : Bhi) + (size_t)(bcol + r) * HID + c * KC + j * 8;
            uint32_t kb = (uint32_t)j * 16;
            uint32_t a = (uint32_t)(r >> 1) * 128
                       + ((((uint32_t)(r & 1)) * 64 + kb) ^ (((uint32_t)(r >> 1) & 7) * 16));
            uint32_t base = (half ? 16384u : 0u) + (comp ? 8192u : 0u);
            cp_async16(stg + base + a, srcp);
        }
    };

    // ---- prologue: edges + chunks 0..2 ----
    int e0 = 0, ecnt = 0;
    if (nt < 8) {
        const int b8 = (blockIdx.y * NREL + nt) * NSUB;
        e0 = boff[b8];
        ecnt = boff[b8 + NSUB] - e0;
        int pn = min(ecnt, ECAP);
        for (int i = tid; i < pn; i += 256)
            cp_async16(sbase + EDG + i * 16, edge + e0 + i);
    }
    issue_chunk(sbase + 0 * STG, 0); cpcommit();
    issue_chunk(sbase + 1 * STG, 1); cpcommit();
    issue_chunk(sbase + 2 * STG, 2); cpcommit();

    // per-lane fragment geometry
    const int arow = lid & 15;
    const uint32_t akoff = (uint32_t)(lid >> 4) * 16;
    const uint32_t asel = (uint32_t)(arow & 1) * 64;
    const uint32_t axorn = (uint32_t)((arow >> 1) & 7) * 16;
    const uint32_t abase = (uint32_t)(wm * 32 + (arow >> 1)) * 128;
    const int brow = (lid & 7) + ((lid >> 4) * 8);
    const uint32_t bkoff = (uint32_t)((lid >> 3) & 1) * 16;
    const uint32_t bsel = (uint32_t)(brow & 1) * 64;
    const uint32_t bxorn = (uint32_t)((brow >> 1) & 7) * 16;
    const uint32_t bbase = (uint32_t)(wn * 16 + (brow >> 1)) * 128;

    float acc[4][4][4];
#pragma unroll
    for (int i = 0; i < 4; i++)
#pragma unroll
        for (int j = 0; j < 4; j++)
#pragma unroll
            for (int v = 0; v < 4; v++) acc[i][j][v] = 0.0f;

    auto compute_chunk = [&](uint32_t stg) {
#pragma unroll
        for (int kk = 0; kk < 2; kk++) {
            uint32_t af[4][4], bf[4][2];
            uint32_t ka = (uint32_t)kk * 32 + akoff;    // 0..48
            uint32_t kb = (uint32_t)kk * 32 + bkoff;

#pragma unroll
            for (int mt = 0; mt < 4; mt++)
                ldmx4(af[mt], stg + abase + (uint32_t)mt * 1024 + ((asel + ka) ^ axorn));
#pragma unroll
            for (int p = 0; p < 2; p++) {
                uint32_t r4[4];
                ldmx4(r4, stg + 24576u + bbase + (uint32_t)p * 1024 + ((bsel + kb) ^ bxorn));
                bf[2 * p][0] = r4[0]; bf[2 * p][1] = r4[1];
                bf[2 * p + 1][0] = r4[2]; bf[2 * p + 1][1] = r4[3];
            }
#pragma unroll
            for (int mt = 0; mt < 4; mt++)
#pragma unroll
                for (int j = 0; j < 4; j++) mma16816(acc[mt][j], af[mt], bf[j]);

#pragma unroll
            for (int p = 0; p < 2; p++) {
                uint32_t r4[4];
                ldmx4(r4, stg + 16384u + bbase + (uint32_t)p * 1024 + ((bsel + kb) ^ bxorn));
                bf[2 * p][0] = r4[0]; bf[2 * p][1] = r4[1];
                bf[2 * p + 1][0] = r4[2]; bf[2 * p + 1][1] = r4[3];
            }
#pragma unroll
            for (int mt = 0; mt < 4; mt++)
#pragma unroll
                for (int j = 0; j < 4; j++) mma16816(acc[mt][j], af[mt], bf[j]);

#pragma unroll
            for (int mt = 0; mt < 4; mt++)
                ldmx4(af[mt], stg + 8192u + abase + (uint32_t)mt * 1024 + ((asel + ka) ^ axorn));
#pragma unroll
            for (int mt = 0; mt < 4; mt++)
#pragma unroll
                for (int j = 0; j < 4; j++) mma16816(acc[mt][j], af[mt], bf[j]);
        }
    };

    // ---- pipelined mainloop: chunks 0..3 over stages mod 3 ----
    cpwait<2>(); __syncthreads();
    compute_chunk(sbase + 0 * STG);
    __syncthreads();                       // all warps done with stage 0
    issue_chunk(sbase + 0 * STG, 3); cpcommit();
    cpwait<2>(); __syncthreads();
    compute_chunk(sbase + 1 * STG);
    cpwait<1>(); __syncthreads();
    compute_chunk(sbase + 2 * STG);
    cpwait<0>(); __syncthreads();
    compute_chunk(sbase + 0 * STG);

    if (nt == 8) {
#pragma unroll
        for (int mt = 0; mt < 4; mt++) {
            int r0 = block_row + wm * 64 + mt * 16 + (lid >> 2);
#pragma unroll
            for (int j = 0; j < 4; j++) {
                int col = wn * 32 + j * 8 + (lid & 3) * 2;
                if (r0 < acc_rows) {
                    float* p = acc_out + (size_t)r0 * HID + col;
                    asm volatile("red.global.add.v2.f32 [%0], {%1, %2};"
                                 :: "l"(p), "f"(acc[mt][j][0]), "f"(acc[mt][j][1]) : "memory");
                }
                if (r0 + 8 < acc_rows) {
                    float* p = acc_out + (size_t)(r0 + 8) * HID + col;
                    asm volatile("red.global.add.v2.f32 [%0], {%1, %2};"
                                 :: "l"(p), "f"(acc[mt][j][2]), "f"(acc[mt][j][3]) : "memory");
                }
            }
        }
        return;
    }

    // relation tile: stage fp32 tile to smem (stages 0-1), scatter bucket edges
    __syncthreads();
#pragma unroll
    for (int mt = 0; mt < 4; mt++) {
        int r0 = wm * 64 + mt * 16 + (lid >> 2);
#pragma unroll
        for (int j = 0; j < 4; j++) {
            int col = wn * 32 + j * 8 + (lid & 3) * 2;
            *(float2*)(stile + r0 * 128 + col)       = make_float2(acc[mt][j][0], acc[mt][j][1]);
            *(float2*)(stile + (r0 + 8) * 128 + col) = make_float2(acc[mt][j][2], acc[mt][j][3]);
        }
    }
    __syncthreads();

    const int pn = min(ecnt, ECAP);
    for (int e = wid; e < pn; e += 8) {
        int4 ed = sedge[e];
        float sc = __int_as_float(ed.z);
        const float4 v = *(const float4*)(stile + (ed.x - block_row) * 128 + lid * 4);
        float4* p = (float4*)(acc_out + (size_t)ed.y * HID) + lid;
        asm volatile("red.global.add.v4.f32 [%0], {%1, %2, %3, %4};"
                     :: "l"(p), "f"(v.x * sc), "f"(v.y * sc), "f"(v.z * sc), "f"(v.w * sc)
                     : "memory");
    }
    for (int e = ECAP + wid; e < ecnt; e += 8) {
        int4 ed = edge[e0 + e];
        float sc = __int_as_float(ed.z);
        const float4 v = *(const float4*)(stile + (ed.x - block_row) * 128 + lid * 4);
        float4* p = (float4*)(acc_out + (size_t)ed.y * HID) + lid;
        asm volatile("red.global.add.v4.f32 [%0], {%1, %2, %3, %4};"
                     :: "l"(p), "f"(v.x * sc), "f"(v.y * sc), "f"(v.z * sc), "f"(v.w * sc)
                     : "memory");
    }
}

// ---------------- launch ----------------
extern "C" void kernel_launch(void* const* d_in, const int* in_sizes, int n_in,
                              void* d_out, int out_size) {
    const int* edge_index = (const int*)d_in[0];
    const int* edge_type  = (const int*)d_in[1];
    const float* node_emb = (const float*)d_in[2];
    const float* W1    = (const float*)d_in[3];
    const float* root1 = (const float*)d_in[4];
    const float* b1    = (const float*)d_in[5];
    const float* W2    = (const float*)d_in[6];
    const float* root2 = (const float*)d_in[7];
    const float* b2    = (const float*)d_in[8];
    float* out = (float*)d_out;

    const int E = in_sizes[0] / 2;
    const int* src = edge_index;
    const int* dst = edge_index + E;

    float *t, *cnt;
    __nv_bfloat16 *xhi, *xlo, *bhi1, *blo1, *bhi2, *blo2;
    int *hist, *cur, *boff;
    int4* edge;
    cudaGetSymbolAddress((void**)&t,    g_t);
    cudaGetSymbolAddress((void**)&cnt,  g_cnt);
    cudaGetSymbolAddress((void**)&xhi,  g_xhi);
    cudaGetSymbolAddress((void**)&xlo,  g_xlo);
    cudaGetSymbolAddress((void**)&bhi1, g_bhi1);
    cudaGetSymbolAddress((void**)&blo1, g_blo1);
    cudaGetSymbolAddress((void**)&bhi2, g_bhi2);
    cudaGetSymbolAddress((void**)&blo2, g_blo2);
    cudaGetSymbolAddress((void**)&hist, g_hist);
    cudaGetSymbolAddress((void**)&cur,  g_cur);
    cudaGetSymbolAddress((void**)&boff, g_boff);
    cudaGetSymbolAddress((void**)&edge, g_edge);

    const int T = 256;
    const dim3 gemm_grid(9, NMB);
    const int SMEM_BYTES = 3 * STG + ECAP * 16;   // 106496
    cudaFuncSetAttribute(gemm_fused, cudaFuncAttributeMaxDynamicSharedMemorySize, SMEM_BYTES);

    // ---- prep ----
    cudaMemsetAsync(cnt, 0, sizeof(float) * (size_t)NN * NREL, 0);
    cudaMemsetAsync(hist, 0, sizeof(int) * NB2, 0);
    counthist_kernel<<<(E + T * 4 - 1) / (T * 4), T>>>(src, dst, edge_type, E, cnt, hist);
    scan_kernel<<<1, 1024>>>(hist, boff, cur);
    prep_kernel<<<RBLK + 2 * BCONV_BLKS + BINIT_T_BLKS + BINIT_O_BLKS + XS_BLKS, T>>>(
        src, dst, edge_type, E, boff, cur, cnt, edge,
        W1, root1, W2, root2, b1, b2, bhi1, blo1, bhi2, blo2, t, out,
        node_emb, xhi, xlo);

    // ---- layer 1 ----
    gemm_fused<<<gemm_grid, T, SMEM_BYTES>>>(xhi, xlo, bhi1, blo1, t, NPAD, edge, boff);
    // ---- layer 2 ----
    xsplit2_kernel<<<XS_BLKS, T>>>(t, xhi, xlo);
    gemm_fused<<<gemm_grid, T, SMEM_BYTES>>>(xhi, xlo, bhi2, blo2, out, NN, edge, boff);
}